// round 3
// baseline (speedup 1.0000x reference)
#include <cuda_runtime.h>
#include <cuda_bf16.h>
#include <cstdint>

// Problem constants (max sizes; runtime values derived from in_sizes)
#define MAXN 100000
#define MAXE 1600000

// ---------------- device scratch (static allocation: allowed) ----------------
__device__ int   g_is64;              // 1 if edge_index is int64, 0 if int32
__device__ int   g_deg[MAXN];
__device__ int   g_off[MAXN + 1];
__device__ int   g_cur[MAXN];
__device__ int   g_bucket[MAXE];
__device__ float g_agg[(size_t)MAXN * 256];  // reused: layer1 (C=128), layer2 (C=256)
__device__ float g_h[(size_t)MAXN * 256];    // hidden activations [N,256]

// ---------------- edge dtype detection ----------------
// If int64 (values < 2^31), every odd 32-bit word is 0. Sample 64 odd words.
__global__ void detect_kernel(const int* __restrict__ w) {
    __shared__ int any;
    if (threadIdx.x == 0) any = 0;
    __syncthreads();
    int v = w[2 * threadIdx.x + 1];
    if (v != 0) atomicOr(&any, 1);
    __syncthreads();
    if (threadIdx.x == 0) g_is64 = (any == 0) ? 1 : 0;
}

__device__ __forceinline__ int load_idx(const void* ei, int E, int pos) {
    // pos in [0, 2E): first E = src, second E = dst
    if (g_is64) {
        long long v = ((const long long*)ei)[pos];
        return (int)v;
    } else {
        return ((const int*)ei)[pos];
    }
}

// ---------------- CSR bucket construction ----------------
__global__ void zero_deg_kernel(int N) {
    int i = blockIdx.x * blockDim.x + threadIdx.x;
    if (i < N) g_deg[i] = 0;
}

__global__ void count_kernel(const void* __restrict__ ei, int E, int N) {
    int e = blockIdx.x * blockDim.x + threadIdx.x;
    if (e < E) {
        int d = load_idx(ei, E, E + e);  // dst
        if ((unsigned)d < (unsigned)N) atomicAdd(&g_deg[d], 1);
    }
}

// Single-block looped exclusive scan over degrees -> offsets, cursor
__global__ void scan_kernel(int N, int E) {
    __shared__ int sh[1024];
    __shared__ int carry;
    int tid = threadIdx.x;
    if (tid == 0) carry = 0;
    __syncthreads();
    for (int base = 0; base < N; base += 1024) {
        int i = base + tid;
        int v = (i < N) ? g_deg[i] : 0;
        sh[tid] = v;
        __syncthreads();
        #pragma unroll
        for (int off = 1; off < 1024; off <<= 1) {
            int t = (tid >= off) ? sh[tid - off] : 0;
            __syncthreads();
            sh[tid] += t;
            __syncthreads();
        }
        int incl = sh[tid];
        int excl = carry + incl - v;
        if (i < N) { g_off[i] = excl; g_cur[i] = excl; }
        __syncthreads();
        if (tid == 1023) carry += incl;
        __syncthreads();
    }
    if (tid == 0) g_off[N] = E;
}

__global__ void fill_kernel(const void* __restrict__ ei, int E, int N) {
    int e = blockIdx.x * blockDim.x + threadIdx.x;
    if (e < E) {
        int s = load_idx(ei, E, e);          // src
        int d = load_idx(ei, E, E + e);      // dst
        if ((unsigned)d < (unsigned)N && (unsigned)s < (unsigned)N) {
            int pos = atomicAdd(&g_cur[d], 1);
            g_bucket[pos] = s;
        }
    }
}

// ---------------- mean aggregation (atomic-free, CSR) ----------------
// One block per node, C/4 threads, float4 per thread.
// SRC_H: feature source is g_h (else the `feat` pointer argument). Output g_agg.
template <int C, bool SRC_H>
__global__ void agg_kernel(const float* __restrict__ feat) {
    const float* __restrict__ src = SRC_H ? (const float*)g_h : feat;
    int n = blockIdx.x;
    int tid = threadIdx.x;  // 0 .. C/4-1
    int beg = g_off[n];
    int end = g_off[n + 1];

    float4 acc = make_float4(0.f, 0.f, 0.f, 0.f);
    int e = beg;
    for (; e + 4 <= end; e += 4) {
        int s0 = g_bucket[e + 0];
        int s1 = g_bucket[e + 1];
        int s2 = g_bucket[e + 2];
        int s3 = g_bucket[e + 3];
        float4 v0 = *reinterpret_cast<const float4*>(&src[(size_t)s0 * C + tid * 4]);
        float4 v1 = *reinterpret_cast<const float4*>(&src[(size_t)s1 * C + tid * 4]);
        float4 v2 = *reinterpret_cast<const float4*>(&src[(size_t)s2 * C + tid * 4]);
        float4 v3 = *reinterpret_cast<const float4*>(&src[(size_t)s3 * C + tid * 4]);
        acc.x += v0.x + v1.x + v2.x + v3.x;
        acc.y += v0.y + v1.y + v2.y + v3.y;
        acc.z += v0.z + v1.z + v2.z + v3.z;
        acc.w += v0.w + v1.w + v2.w + v3.w;
    }
    for (; e < end; ++e) {
        int s = g_bucket[e];
        float4 v = *reinterpret_cast<const float4*>(&src[(size_t)s * C + tid * 4]);
        acc.x += v.x; acc.y += v.y; acc.z += v.z; acc.w += v.w;
    }
    float inv = (end > beg) ? 1.f / (float)(end - beg) : 0.f;
    acc.x *= inv; acc.y *= inv; acc.z *= inv; acc.w *= inv;
    *reinterpret_cast<float4*>(&g_agg[(size_t)n * C + tid * 4]) = acc;
}

// ---------------- fused dual GEMM + bias + activation ----------------
// C[M,NO] = act(g_agg[M,K1] @ W1 + A2[M,K1] @ W2 + bias)
// A2 is g_h if A2_H else `A2p`. Output is g_h if OUT_H else `Coutp`.
// Block tile 128x64, 256 threads, per-thread 8x4. ACT: 0=relu, 1=sigmoid.
template <int ACT, bool A2_H, bool OUT_H>
__global__ void gemm_dual(const float* __restrict__ A2p,
                          const float* __restrict__ W1, const float* __restrict__ W2,
                          const float* __restrict__ bias, float* __restrict__ Coutp,
                          int M, int K1, int NO) {
    const float* __restrict__ A1 = (const float*)g_agg;
    const float* __restrict__ A2full = A2_H ? (const float*)g_h : A2p;
    float* __restrict__ Cout = OUT_H ? (float*)g_h : Coutp;

    const int BM = 128, BN = 64, BK = 16;
    __shared__ float As[BK][BM + 4];
    __shared__ float Ws[BK][BN + 4];

    int tx = threadIdx.x & 15;   // 0..15
    int ty = threadIdx.x >> 4;   // 0..15
    int row0 = blockIdx.y * BM;
    int col0 = blockIdx.x * BN;

    float acc[8][4];
    #pragma unroll
    for (int i = 0; i < 8; i++)
        #pragma unroll
        for (int j = 0; j < 4; j++) acc[i][j] = 0.f;

    for (int half = 0; half < 2; ++half) {
        const float* __restrict__ A = half ? A2full : A1;
        const float* __restrict__ W = half ? W2 : W1;
        for (int k0 = 0; k0 < K1; k0 += BK) {
            // Load A tile: 128 rows x 16 k. 256 threads, 2 float4 each.
            {
                int t = threadIdx.x;
                int r = t >> 1;              // 0..127
                int kk = (t & 1) * 8;        // 0 or 8
                int grow = row0 + r;
                float4 v0 = make_float4(0, 0, 0, 0);
                float4 v1 = make_float4(0, 0, 0, 0);
                if (grow < M) {
                    const float* ap = &A[(size_t)grow * K1 + k0 + kk];
                    v0 = *reinterpret_cast<const float4*>(ap);
                    v1 = *reinterpret_cast<const float4*>(ap + 4);
                }
                As[kk + 0][r] = v0.x; As[kk + 1][r] = v0.y;
                As[kk + 2][r] = v0.z; As[kk + 3][r] = v0.w;
                As[kk + 4][r] = v1.x; As[kk + 5][r] = v1.y;
                As[kk + 6][r] = v1.z; As[kk + 7][r] = v1.w;
            }
            // Load W tile: 16 k x 64 cols. 1 float4 per thread.
            {
                int t = threadIdx.x;
                int kk = t >> 4;             // 0..15
                int c = (t & 15) * 4;        // 0..60
                float4 v = *reinterpret_cast<const float4*>(&W[(size_t)(k0 + kk) * NO + col0 + c]);
                Ws[kk][c + 0] = v.x; Ws[kk][c + 1] = v.y;
                Ws[kk][c + 2] = v.z; Ws[kk][c + 3] = v.w;
            }
            __syncthreads();
            #pragma unroll
            for (int kk = 0; kk < BK; ++kk) {
                float a[8], w[4];
                #pragma unroll
                for (int i = 0; i < 8; i++) a[i] = As[kk][ty * 8 + i];
                #pragma unroll
                for (int j = 0; j < 4; j++) w[j] = Ws[kk][tx * 4 + j];
                #pragma unroll
                for (int i = 0; i < 8; i++)
                    #pragma unroll
                    for (int j = 0; j < 4; j++)
                        acc[i][j] = fmaf(a[i], w[j], acc[i][j]);
            }
            __syncthreads();
        }
    }

    // Epilogue: bias + activation, vectorized stores
    int cbase = col0 + tx * 4;
    float4 bv = *reinterpret_cast<const float4*>(&bias[cbase]);
    #pragma unroll
    for (int i = 0; i < 8; i++) {
        int r = row0 + ty * 8 + i;
        if (r >= M) continue;
        float4 o;
        o.x = acc[i][0] + bv.x;
        o.y = acc[i][1] + bv.y;
        o.z = acc[i][2] + bv.z;
        o.w = acc[i][3] + bv.w;
        if (ACT == 0) {
            o.x = fmaxf(o.x, 0.f); o.y = fmaxf(o.y, 0.f);
            o.z = fmaxf(o.z, 0.f); o.w = fmaxf(o.w, 0.f);
        } else {
            o.x = 1.f / (1.f + __expf(-o.x));
            o.y = 1.f / (1.f + __expf(-o.y));
            o.z = 1.f / (1.f + __expf(-o.z));
            o.w = 1.f / (1.f + __expf(-o.w));
        }
        *reinterpret_cast<float4*>(&Cout[(size_t)r * NO + cbase]) = o;
    }
}

// ---------------- launch ----------------
extern "C" void kernel_launch(void* const* d_in, const int* in_sizes, int n_in,
                              void* d_out, int out_size) {
    const float* x   = (const float*)d_in[0];
    const void*  ei  = d_in[1];
    const float* W1l = (const float*)d_in[2];
    const float* W1r = (const float*)d_in[3];
    const float* b1  = (const float*)d_in[4];
    const float* W2l = (const float*)d_in[5];
    const float* W2r = (const float*)d_in[6];
    const float* b2  = (const float*)d_in[7];
    float* out = (float*)d_out;

    int N = in_sizes[0] / 128;   // 100000
    int E = in_sizes[1] / 2;     // 1600000 (element count is dtype-agnostic here)

    // 0) Detect edge_index dtype (int32 vs int64)
    detect_kernel<<<1, 64>>>((const int*)ei);

    // 1) CSR buckets
    zero_deg_kernel<<<(N + 255) / 256, 256>>>(N);
    count_kernel<<<(E + 255) / 256, 256>>>(ei, E, N);
    scan_kernel<<<1, 1024>>>(N, E);
    fill_kernel<<<(E + 255) / 256, 256>>>(ei, E, N);

    // 2) Layer 1: agg over x (C=128) -> g_agg, then g_h = relu([g_agg|x] @ [W1l;W1r] + b1)
    agg_kernel<128, false><<<N, 32>>>(x);
    {
        dim3 grid(256 / 64, (N + 127) / 128);
        gemm_dual<0, false, true><<<grid, 256>>>(x, W1l, W1r, b1, nullptr, N, 128, 256);
    }

    // 3) Layer 2: agg over g_h (C=256) -> g_agg, then out = sigmoid([g_agg|g_h] @ [W2l;W2r] + b2)
    agg_kernel<256, true><<<N, 64>>>(nullptr);
    {
        dim3 grid(64 / 64, (N + 127) / 128);
        gemm_dual<1, true, false><<<grid, 256>>>(nullptr, W2l, W2r, b2, out, N, 256, 64);
    }
}

// round 4
// speedup vs baseline: 1.3712x; 1.3712x over previous
#include <cuda_runtime.h>
#include <cuda_bf16.h>
#include <cstdint>

#define MAXN 100000
#define MAXE 1600000
#define MAXB ((MAXN + 1023) / 1024)   // 98 scan blocks

// ---------------- device scratch ----------------
__device__ int   g_is64;
__device__ int   g_deg[MAXN];
__device__ int   g_off[MAXN + 1];
__device__ int   g_cur[MAXN];
__device__ int   g_bsum[128];
__device__ int   g_bucket[MAXE];
__device__ float g_agg[(size_t)MAXN * 128];  // layer1 aggregated x
__device__ float g_h[(size_t)MAXN * 256];    // hidden activations
__device__ float g_tu[(size_t)MAXN * 128];   // layer2: [t(64) | u(64)] per node

// ---------------- edge dtype detection ----------------
__global__ void detect_kernel(const int* __restrict__ w) {
    __shared__ int any;
    if (threadIdx.x == 0) any = 0;
    __syncthreads();
    if (w[2 * threadIdx.x + 1] != 0) atomicOr(&any, 1);
    __syncthreads();
    if (threadIdx.x == 0) g_is64 = (any == 0) ? 1 : 0;
}

__device__ __forceinline__ int load_idx(const void* ei, int pos) {
    if (g_is64) return (int)((const long long*)ei)[pos];
    return ((const int*)ei)[pos];
}

// ---------------- CSR construction ----------------
__global__ void zero_deg_kernel(int N) {
    int i = blockIdx.x * blockDim.x + threadIdx.x;
    if (i < N) g_deg[i] = 0;
}

__global__ void count_kernel(const void* __restrict__ ei, int E, int N) {
    int e = blockIdx.x * blockDim.x + threadIdx.x;
    if (e < E) {
        int d = load_idx(ei, E + e);
        if ((unsigned)d < (unsigned)N) atomicAdd(&g_deg[d], 1);
    }
}

// Per-block exclusive scan (1024 elems/block) via warp shuffles; block sums out.
__global__ void scan_blocks(int N) {
    __shared__ int wsum[32];
    int i = blockIdx.x * 1024 + threadIdx.x;
    int lane = threadIdx.x & 31, wid = threadIdx.x >> 5;
    int v = (i < N) ? g_deg[i] : 0;
    int s = v;
    #pragma unroll
    for (int o = 1; o < 32; o <<= 1) {
        int t = __shfl_up_sync(0xffffffffu, s, o);
        if (lane >= o) s += t;
    }
    if (lane == 31) wsum[wid] = s;
    __syncthreads();
    if (wid == 0) {
        int ws = wsum[lane];
        #pragma unroll
        for (int o = 1; o < 32; o <<= 1) {
            int t = __shfl_up_sync(0xffffffffu, ws, o);
            if (lane >= o) ws += t;
        }
        wsum[lane] = ws;
    }
    __syncthreads();
    int incl = s + (wid > 0 ? wsum[wid - 1] : 0);
    if (i < N) g_off[i] = incl - v;               // block-local exclusive
    if (threadIdx.x == 1023) g_bsum[blockIdx.x] = incl;  // block total
}

// Scan the (<=128) block sums with one warp.
__global__ void scan_bsums(int B) {
    int lane = threadIdx.x;
    int carry = 0;
    for (int base = 0; base < B; base += 32) {
        int i = base + lane;
        int v = (i < B) ? g_bsum[i] : 0;
        int s = v;
        #pragma unroll
        for (int o = 1; o < 32; o <<= 1) {
            int t = __shfl_up_sync(0xffffffffu, s, o);
            if (lane >= o) s += t;
        }
        if (i < B) g_bsum[i] = carry + s - v;
        carry += __shfl_sync(0xffffffffu, s, 31);
    }
}

__global__ void finalize_off(int N, int E) {
    int i = blockIdx.x * blockDim.x + threadIdx.x;
    if (i < N) {
        int o = g_off[i] + g_bsum[i >> 10];
        g_off[i] = o;
        g_cur[i] = o;
    }
    if (i == 0) g_off[N] = E;
}

__global__ void fill_kernel(const void* __restrict__ ei, int E, int N) {
    int e = blockIdx.x * blockDim.x + threadIdx.x;
    if (e < E) {
        int s = load_idx(ei, e);
        int d = load_idx(ei, E + e);
        if ((unsigned)d < (unsigned)N && (unsigned)s < (unsigned)N) {
            int pos = atomicAdd(&g_cur[d], 1);
            g_bucket[pos] = s;
        }
    }
}

// ---------------- layer-1 mean aggregation (C=128) ----------------
__global__ void agg128_kernel(const float* __restrict__ x) {
    int n = blockIdx.x;
    int tid = threadIdx.x;  // 0..31, float4 lane
    int beg = g_off[n], end = g_off[n + 1];
    float4 acc = make_float4(0.f, 0.f, 0.f, 0.f);
    int e = beg;
    for (; e + 4 <= end; e += 4) {
        int s0 = g_bucket[e], s1 = g_bucket[e + 1], s2 = g_bucket[e + 2], s3 = g_bucket[e + 3];
        float4 v0 = *(const float4*)&x[(size_t)s0 * 128 + tid * 4];
        float4 v1 = *(const float4*)&x[(size_t)s1 * 128 + tid * 4];
        float4 v2 = *(const float4*)&x[(size_t)s2 * 128 + tid * 4];
        float4 v3 = *(const float4*)&x[(size_t)s3 * 128 + tid * 4];
        acc.x += v0.x + v1.x + v2.x + v3.x;
        acc.y += v0.y + v1.y + v2.y + v3.y;
        acc.z += v0.z + v1.z + v2.z + v3.z;
        acc.w += v0.w + v1.w + v2.w + v3.w;
    }
    for (; e < end; ++e) {
        int s = g_bucket[e];
        float4 v = *(const float4*)&x[(size_t)s * 128 + tid * 4];
        acc.x += v.x; acc.y += v.y; acc.z += v.z; acc.w += v.w;
    }
    float inv = (end > beg) ? 1.f / (float)(end - beg) : 0.f;
    acc.x *= inv; acc.y *= inv; acc.z *= inv; acc.w *= inv;
    *(float4*)&g_agg[(size_t)n * 128 + tid * 4] = acc;
}

// ---------------- unified GEMM ----------------
// MODE 0: g_h = relu( [g_agg | x] (K=256) @ [W1l ; W1r] + b1 ),  NO=256
// MODE 1: g_tu = g_h (K=256) @ [W2l | W2r] (col-concat),         NO=128, raw
// Tile 128x128, BK=16, 256 threads, 8x8 per thread.
template <int MODE>
__global__ void __launch_bounds__(256, 2)
gemm_k(const float* __restrict__ x,
       const float* __restrict__ Wa, const float* __restrict__ Wb,
       const float* __restrict__ bias, int M) {
    const int BM = 128, BN = 128, BK = 16;
    __shared__ float As[BK][BM + 4];
    __shared__ float Ws[BK][BN + 4];

    int tx = threadIdx.x & 15;
    int ty = threadIdx.x >> 4;
    int row0 = blockIdx.y * BM;
    int col0 = blockIdx.x * BN;

    float acc[8][8];
    #pragma unroll
    for (int i = 0; i < 8; i++)
        #pragma unroll
        for (int j = 0; j < 8; j++) acc[i][j] = 0.f;

    for (int k0 = 0; k0 < 256; k0 += BK) {
        // ---- A tile: 128 rows x 16 k; 2 float4 per thread ----
        {
            int t = threadIdx.x;
            int r = t >> 1;
            int kk = (t & 1) * 8;
            int grow = row0 + r;
            const float* A;
            int kloc, stride;
            if (MODE == 0) {
                A = (k0 < 128) ? (const float*)g_agg : x;
                kloc = k0 & 127; stride = 128;
            } else {
                A = (const float*)g_h;
                kloc = k0; stride = 256;
            }
            float4 v0 = make_float4(0, 0, 0, 0), v1 = make_float4(0, 0, 0, 0);
            if (grow < M) {
                const float* ap = &A[(size_t)grow * stride + kloc + kk];
                v0 = *(const float4*)ap;
                v1 = *(const float4*)(ap + 4);
            }
            As[kk + 0][r] = v0.x; As[kk + 1][r] = v0.y;
            As[kk + 2][r] = v0.z; As[kk + 3][r] = v0.w;
            As[kk + 4][r] = v1.x; As[kk + 5][r] = v1.y;
            As[kk + 6][r] = v1.z; As[kk + 7][r] = v1.w;
        }
        // ---- W tile: 16 k x 128 cols; 2 float4 per thread ----
        {
            int t = threadIdx.x;
            int kk = t >> 4;            // 0..15
            int c = (t & 15) * 8;       // 0..120
            float4 v0, v1;
            if (MODE == 0) {
                const float* Wsrc = (k0 < 128) ? Wa : Wb;
                int kr = (k0 & 127) + kk;
                const float* wp = &Wsrc[(size_t)kr * 256 + col0 + c];
                v0 = *(const float4*)wp;
                v1 = *(const float4*)(wp + 4);
            } else {
                int k = k0 + kk;
                // col-concat: c<64 -> Wa (64 cols), else Wb
                const float* wp0 = (c < 64) ? &Wa[(size_t)k * 64 + c]
                                            : &Wb[(size_t)k * 64 + (c - 64)];
                const float* wp1 = (c + 4 < 64) ? &Wa[(size_t)k * 64 + c + 4]
                                                : &Wb[(size_t)k * 64 + (c + 4 - 64)];
                v0 = *(const float4*)wp0;
                v1 = *(const float4*)wp1;
            }
            Ws[kk][c + 0] = v0.x; Ws[kk][c + 1] = v0.y;
            Ws[kk][c + 2] = v0.z; Ws[kk][c + 3] = v0.w;
            Ws[kk][c + 4] = v1.x; Ws[kk][c + 5] = v1.y;
            Ws[kk][c + 6] = v1.z; Ws[kk][c + 7] = v1.w;
        }
        __syncthreads();
        #pragma unroll
        for (int kk = 0; kk < BK; ++kk) {
            float a[8], w[8];
            #pragma unroll
            for (int i = 0; i < 8; i++) a[i] = As[kk][ty * 8 + i];
            #pragma unroll
            for (int j = 0; j < 8; j++) w[j] = Ws[kk][tx * 8 + j];
            #pragma unroll
            for (int i = 0; i < 8; i++)
                #pragma unroll
                for (int j = 0; j < 8; j++)
                    acc[i][j] = fmaf(a[i], w[j], acc[i][j]);
        }
        __syncthreads();
    }

    // ---- epilogue ----
    int cbase = col0 + tx * 8;
    if (MODE == 0) {
        float4 bv0 = *(const float4*)&bias[cbase];
        float4 bv1 = *(const float4*)&bias[cbase + 4];
        #pragma unroll
        for (int i = 0; i < 8; i++) {
            int r = row0 + ty * 8 + i;
            if (r >= M) continue;
            float4 o0, o1;
            o0.x = fmaxf(acc[i][0] + bv0.x, 0.f);
            o0.y = fmaxf(acc[i][1] + bv0.y, 0.f);
            o0.z = fmaxf(acc[i][2] + bv0.z, 0.f);
            o0.w = fmaxf(acc[i][3] + bv0.w, 0.f);
            o1.x = fmaxf(acc[i][4] + bv1.x, 0.f);
            o1.y = fmaxf(acc[i][5] + bv1.y, 0.f);
            o1.z = fmaxf(acc[i][6] + bv1.z, 0.f);
            o1.w = fmaxf(acc[i][7] + bv1.w, 0.f);
            float* hp = &g_h[(size_t)r * 256 + cbase];
            *(float4*)hp = o0;
            *(float4*)(hp + 4) = o1;
        }
    } else {
        #pragma unroll
        for (int i = 0; i < 8; i++) {
            int r = row0 + ty * 8 + i;
            if (r >= M) continue;
            float4 o0 = make_float4(acc[i][0], acc[i][1], acc[i][2], acc[i][3]);
            float4 o1 = make_float4(acc[i][4], acc[i][5], acc[i][6], acc[i][7]);
            float* tp = &g_tu[(size_t)r * 128 + cbase];
            *(float4*)tp = o0;
            *(float4*)(tp + 4) = o1;
        }
    }
}

// ---------------- final: out = sigmoid( mean_agg(t) + u + b2 ) ----------------
// 16 threads per node (C=64, float4 lanes), 8 nodes per 128-thread block.
__global__ void agg_sig_kernel(const float* __restrict__ b2, float* __restrict__ out, int N) {
    int lane = threadIdx.x & 15;
    int node = blockIdx.x * 8 + (threadIdx.x >> 4);
    if (node >= N) return;
    int beg = g_off[node], end = g_off[node + 1];
    float4 acc = make_float4(0.f, 0.f, 0.f, 0.f);
    int e = beg;
    for (; e + 2 <= end; e += 2) {
        int s0 = g_bucket[e], s1 = g_bucket[e + 1];
        float4 v0 = *(const float4*)&g_tu[(size_t)s0 * 128 + lane * 4];
        float4 v1 = *(const float4*)&g_tu[(size_t)s1 * 128 + lane * 4];
        acc.x += v0.x + v1.x; acc.y += v0.y + v1.y;
        acc.z += v0.z + v1.z; acc.w += v0.w + v1.w;
    }
    for (; e < end; ++e) {
        int s = g_bucket[e];
        float4 v = *(const float4*)&g_tu[(size_t)s * 128 + lane * 4];
        acc.x += v.x; acc.y += v.y; acc.z += v.z; acc.w += v.w;
    }
    float inv = (end > beg) ? 1.f / (float)(end - beg) : 0.f;
    float4 u = *(const float4*)&g_tu[(size_t)node * 128 + 64 + lane * 4];
    float4 bv = *(const float4*)&b2[lane * 4];
    float4 o;
    o.x = 1.f / (1.f + __expf(-(acc.x * inv + u.x + bv.x)));
    o.y = 1.f / (1.f + __expf(-(acc.y * inv + u.y + bv.y)));
    o.z = 1.f / (1.f + __expf(-(acc.z * inv + u.z + bv.z)));
    o.w = 1.f / (1.f + __expf(-(acc.w * inv + u.w + bv.w)));
    *(float4*)&out[(size_t)node * 64 + lane * 4] = o;
}

// ---------------- launch ----------------
extern "C" void kernel_launch(void* const* d_in, const int* in_sizes, int n_in,
                              void* d_out, int out_size) {
    const float* x   = (const float*)d_in[0];
    const void*  ei  = d_in[1];
    const float* W1l = (const float*)d_in[2];
    const float* W1r = (const float*)d_in[3];
    const float* b1  = (const float*)d_in[4];
    const float* W2l = (const float*)d_in[5];
    const float* W2r = (const float*)d_in[6];
    const float* b2  = (const float*)d_in[7];
    float* out = (float*)d_out;

    int N = in_sizes[0] / 128;   // 100000
    int E = in_sizes[1] / 2;     // 1600000
    int B = (N + 1023) / 1024;   // scan blocks

    // 0) dtype detect + CSR build
    detect_kernel<<<1, 64>>>((const int*)ei);
    zero_deg_kernel<<<(N + 255) / 256, 256>>>(N);
    count_kernel<<<(E + 255) / 256, 256>>>(ei, E, N);
    scan_blocks<<<B, 1024>>>(N);
    scan_bsums<<<1, 32>>>(B);
    finalize_off<<<(N + 255) / 256, 256>>>(N, E);
    fill_kernel<<<(E + 255) / 256, 256>>>(ei, E, N);

    // 1) layer 1: agg(x) -> g_agg; g_h = relu([g_agg|x] @ [W1l;W1r] + b1)
    agg128_kernel<<<N, 32>>>(x);
    {
        dim3 grid(256 / 128, (N + 127) / 128);
        gemm_k<0><<<grid, 256>>>(x, W1l, W1r, b1, N);
    }

    // 2) layer 2: [t|u] = g_h @ [W2l|W2r]; out = sigmoid(mean_agg(t) + u + b2)
    {
        dim3 grid(1, (N + 127) / 128);
        gemm_k<1><<<grid, 256>>>(nullptr, W2l, W2r, nullptr, N);
    }
    agg_sig_kernel<<<(N + 7) / 8, 128>>>(b2, out, N);
}

// round 5
// speedup vs baseline: 2.7688x; 2.0193x over previous
#include <cuda_runtime.h>
#include <cuda_bf16.h>
#include <cstdint>

#define MAXN 100000
#define MAXE 1600000

// ---------------- device scratch ----------------
__device__ int   g_is64;
__device__ int   g_deg[MAXN];
__device__ int   g_off[MAXN + 1];
__device__ int   g_cur[MAXN];
__device__ int   g_bsum[128];
__device__ int   g_bucket[MAXE];
__device__ float g_agg[(size_t)MAXN * 128];  // layer1 aggregated x
__device__ float g_h[(size_t)MAXN * 256];    // hidden activations
__device__ float g_tu[(size_t)MAXN * 128];   // layer2: [t(64) | u(64)]

// ---------------- edge dtype detection ----------------
__global__ void detect_kernel(const int* __restrict__ w) {
    __shared__ int any;
    if (threadIdx.x == 0) any = 0;
    __syncthreads();
    if (w[2 * threadIdx.x + 1] != 0) atomicOr(&any, 1);
    __syncthreads();
    if (threadIdx.x == 0) g_is64 = (any == 0) ? 1 : 0;
}

__device__ __forceinline__ int load_idx(const void* ei, int pos) {
    if (g_is64) return (int)((const long long*)ei)[pos];
    return ((const int*)ei)[pos];
}

// ---------------- CSR construction ----------------
__global__ void zero_deg_kernel(int N) {
    int i = blockIdx.x * blockDim.x + threadIdx.x;
    if (i < N) g_deg[i] = 0;
}

__global__ void count_kernel(const void* __restrict__ ei, int E, int N) {
    int e = blockIdx.x * blockDim.x + threadIdx.x;
    if (e < E) {
        int d = load_idx(ei, E + e);
        if ((unsigned)d < (unsigned)N) atomicAdd(&g_deg[d], 1);
    }
}

__global__ void scan_blocks(int N) {
    __shared__ int wsum[32];
    int i = blockIdx.x * 1024 + threadIdx.x;
    int lane = threadIdx.x & 31, wid = threadIdx.x >> 5;
    int v = (i < N) ? g_deg[i] : 0;
    int s = v;
    #pragma unroll
    for (int o = 1; o < 32; o <<= 1) {
        int t = __shfl_up_sync(0xffffffffu, s, o);
        if (lane >= o) s += t;
    }
    if (lane == 31) wsum[wid] = s;
    __syncthreads();
    if (wid == 0) {
        int ws = wsum[lane];
        #pragma unroll
        for (int o = 1; o < 32; o <<= 1) {
            int t = __shfl_up_sync(0xffffffffu, ws, o);
            if (lane >= o) ws += t;
        }
        wsum[lane] = ws;
    }
    __syncthreads();
    int incl = s + (wid > 0 ? wsum[wid - 1] : 0);
    if (i < N) g_off[i] = incl - v;
    if (threadIdx.x == 1023) g_bsum[blockIdx.x] = incl;
}

__global__ void scan_bsums(int B) {
    int lane = threadIdx.x;
    int carry = 0;
    for (int base = 0; base < B; base += 32) {
        int i = base + lane;
        int v = (i < B) ? g_bsum[i] : 0;
        int s = v;
        #pragma unroll
        for (int o = 1; o < 32; o <<= 1) {
            int t = __shfl_up_sync(0xffffffffu, s, o);
            if (lane >= o) s += t;
        }
        if (i < B) g_bsum[i] = carry + s - v;
        carry += __shfl_sync(0xffffffffu, s, 31);
    }
}

__global__ void finalize_off(int N, int E) {
    int i = blockIdx.x * blockDim.x + threadIdx.x;
    if (i < N) {
        int o = g_off[i] + g_bsum[i >> 10];
        g_off[i] = o;
        g_cur[i] = o;
    }
    if (i == 0) g_off[N] = E;
}

__global__ void fill_kernel(const void* __restrict__ ei, int E, int N) {
    int e = blockIdx.x * blockDim.x + threadIdx.x;
    if (e < E) {
        int s = load_idx(ei, e);
        int d = load_idx(ei, E + e);
        if ((unsigned)d < (unsigned)N && (unsigned)s < (unsigned)N) {
            int pos = atomicAdd(&g_cur[d], 1);
            g_bucket[pos] = s;
        }
    }
}

// ---------------- layer-1 mean aggregation (C=128), warp per node ----------------
__global__ void agg128_kernel(const float* __restrict__ x, int N) {
    int lane = threadIdx.x & 31;
    int node = blockIdx.x * 4 + (threadIdx.x >> 5);
    if (node >= N) return;
    int beg = g_off[node], end = g_off[node + 1];
    float4 acc = make_float4(0.f, 0.f, 0.f, 0.f);
    int e = beg;
    for (; e + 4 <= end; e += 4) {
        int s0 = g_bucket[e], s1 = g_bucket[e + 1], s2 = g_bucket[e + 2], s3 = g_bucket[e + 3];
        float4 v0 = *(const float4*)&x[(size_t)s0 * 128 + lane * 4];
        float4 v1 = *(const float4*)&x[(size_t)s1 * 128 + lane * 4];
        float4 v2 = *(const float4*)&x[(size_t)s2 * 128 + lane * 4];
        float4 v3 = *(const float4*)&x[(size_t)s3 * 128 + lane * 4];
        acc.x += v0.x + v1.x + v2.x + v3.x;
        acc.y += v0.y + v1.y + v2.y + v3.y;
        acc.z += v0.z + v1.z + v2.z + v3.z;
        acc.w += v0.w + v1.w + v2.w + v3.w;
    }
    for (; e < end; ++e) {
        int s = g_bucket[e];
        float4 v = *(const float4*)&x[(size_t)s * 128 + lane * 4];
        acc.x += v.x; acc.y += v.y; acc.z += v.z; acc.w += v.w;
    }
    float inv = (end > beg) ? 1.f / (float)(end - beg) : 0.f;
    acc.x *= inv; acc.y *= inv; acc.z *= inv; acc.w *= inv;
    *(float4*)&g_agg[(size_t)node * 128 + lane * 4] = acc;
}

// ---------------- TF32 tensor-core GEMM ----------------
// MODE 0: g_h = relu( [g_agg | x] (K=256) @ [W1l ; W1r] + b1 ),  NO=256
// MODE 1: g_tu = g_h (K=256) @ [W2l | W2r] (col-concat),         NO=128
// Block tile 128x128, BK=32, 256 threads = 8 warps (2m x 4n), warp tile 64x32.
// mma.sync.m16n8k8 tf32.

__device__ __forceinline__ unsigned f2tf32(float v) {
    unsigned r;
    asm("cvt.rna.tf32.f32 %0, %1;" : "=r"(r) : "f"(v));
    return r;
}

template <int MODE>
__global__ void __launch_bounds__(256, 2)
gemm_tc(const float* __restrict__ x,
        const float* __restrict__ Wa, const float* __restrict__ Wb,
        const float* __restrict__ bias, int M) {
    // strides chosen for conflict-free fragment reads:
    // As: addr%32 = 4m+k pattern (36 ≡ 4 mod 32); Ws: 8k+n pattern (136 ≡ 8 mod 32)
    __shared__ unsigned As[128][36];
    __shared__ unsigned Ws[32][136];

    int tid = threadIdx.x;
    int lane = tid & 31;
    int wid = tid >> 5;
    int warp_m = wid & 1;        // 0..1, 64 rows each
    int warp_n = wid >> 1;       // 0..3, 32 cols each
    int qk = lane & 3;
    int qr = lane >> 2;

    int row0 = blockIdx.y * 128;
    int col0 = blockIdx.x * 128;

    float d[4][4][4];
    #pragma unroll
    for (int i = 0; i < 4; i++)
        #pragma unroll
        for (int j = 0; j < 4; j++)
            #pragma unroll
            for (int q = 0; q < 4; q++) d[i][j][q] = 0.f;

    for (int k0 = 0; k0 < 256; k0 += 32) {
        // ---- fill A tile (128 x 32): 4 float4 per thread ----
        #pragma unroll
        for (int it = 0; it < 4; it++) {
            int f = tid + it * 256;          // 0..1023
            int m = f >> 3;                  // row 0..127
            int k = (f & 7) * 4;             // 0..28
            int grow = row0 + m;
            float4 v = make_float4(0, 0, 0, 0);
            if (grow < M) {
                if (MODE == 0) {
                    const float* A = (k0 < 128) ? (const float*)g_agg : x;
                    v = *(const float4*)&A[(size_t)grow * 128 + (k0 & 127) + k];
                } else {
                    v = *(const float4*)&g_h[(size_t)grow * 256 + k0 + k];
                }
            }
            As[m][k + 0] = f2tf32(v.x); As[m][k + 1] = f2tf32(v.y);
            As[m][k + 2] = f2tf32(v.z); As[m][k + 3] = f2tf32(v.w);
        }
        // ---- fill W tile (32 x 128): 4 float4 per thread ----
        #pragma unroll
        for (int it = 0; it < 4; it++) {
            int f = tid + it * 256;
            int k = f >> 5;                  // 0..31
            int n = (f & 31) * 4;            // 0..124
            float4 v;
            if (MODE == 0) {
                const float* Wsrc = (k0 < 128) ? Wa : Wb;
                v = *(const float4*)&Wsrc[(size_t)((k0 & 127) + k) * 256 + col0 + n];
            } else {
                int kg = k0 + k;
                v = (n < 64) ? *(const float4*)&Wa[(size_t)kg * 64 + n]
                             : *(const float4*)&Wb[(size_t)kg * 64 + (n - 64)];
            }
            Ws[k][n + 0] = f2tf32(v.x); Ws[k][n + 1] = f2tf32(v.y);
            Ws[k][n + 2] = f2tf32(v.z); Ws[k][n + 3] = f2tf32(v.w);
        }
        __syncthreads();

        // ---- compute: 4 k8 steps ----
        #pragma unroll
        for (int k8 = 0; k8 < 32; k8 += 8) {
            unsigned a[4][4], b[4][2];
            #pragma unroll
            for (int mf = 0; mf < 4; mf++) {
                int mrow = warp_m * 64 + mf * 16 + qr;
                a[mf][0] = As[mrow][k8 + qk];
                a[mf][1] = As[mrow + 8][k8 + qk];
                a[mf][2] = As[mrow][k8 + qk + 4];
                a[mf][3] = As[mrow + 8][k8 + qk + 4];
            }
            #pragma unroll
            for (int nf = 0; nf < 4; nf++) {
                int ncol = warp_n * 32 + nf * 8 + qr;
                b[nf][0] = Ws[k8 + qk][ncol];
                b[nf][1] = Ws[k8 + qk + 4][ncol];
            }
            #pragma unroll
            for (int mf = 0; mf < 4; mf++)
                #pragma unroll
                for (int nf = 0; nf < 4; nf++) {
                    asm volatile(
                        "mma.sync.aligned.m16n8k8.row.col.f32.tf32.tf32.f32 "
                        "{%0,%1,%2,%3}, {%4,%5,%6,%7}, {%8,%9}, {%0,%1,%2,%3};"
                        : "+f"(d[mf][nf][0]), "+f"(d[mf][nf][1]),
                          "+f"(d[mf][nf][2]), "+f"(d[mf][nf][3])
                        : "r"(a[mf][0]), "r"(a[mf][1]), "r"(a[mf][2]), "r"(a[mf][3]),
                          "r"(b[nf][0]), "r"(b[nf][1]));
                }
        }
        __syncthreads();
    }

    // ---- epilogue ----
    #pragma unroll
    for (int nf = 0; nf < 4; nf++) {
        int col = col0 + warp_n * 32 + nf * 8 + qk * 2;
        float2 bv = make_float2(0.f, 0.f);
        if (MODE == 0) bv = *(const float2*)&bias[col];
        #pragma unroll
        for (int mf = 0; mf < 4; mf++) {
            int r0 = row0 + warp_m * 64 + mf * 16 + qr;
            if (MODE == 0) {
                if (r0 < M) {
                    float2 o = make_float2(fmaxf(d[mf][nf][0] + bv.x, 0.f),
                                           fmaxf(d[mf][nf][1] + bv.y, 0.f));
                    *(float2*)&g_h[(size_t)r0 * 256 + col] = o;
                }
                if (r0 + 8 < M) {
                    float2 o = make_float2(fmaxf(d[mf][nf][2] + bv.x, 0.f),
                                           fmaxf(d[mf][nf][3] + bv.y, 0.f));
                    *(float2*)&g_h[(size_t)(r0 + 8) * 256 + col] = o;
                }
            } else {
                if (r0 < M) {
                    float2 o = make_float2(d[mf][nf][0], d[mf][nf][1]);
                    *(float2*)&g_tu[(size_t)r0 * 128 + col] = o;
                }
                if (r0 + 8 < M) {
                    float2 o = make_float2(d[mf][nf][2], d[mf][nf][3]);
                    *(float2*)&g_tu[(size_t)(r0 + 8) * 128 + col] = o;
                }
            }
        }
    }
}

// ---------------- final: out = sigmoid( mean_agg(t) + u + b2 ) ----------------
__global__ void agg_sig_kernel(const float* __restrict__ b2, float* __restrict__ out, int N) {
    int lane = threadIdx.x & 15;
    int node = blockIdx.x * 8 + (threadIdx.x >> 4);
    if (node >= N) return;
    int beg = g_off[node], end = g_off[node + 1];
    float4 acc = make_float4(0.f, 0.f, 0.f, 0.f);
    int e = beg;
    for (; e + 2 <= end; e += 2) {
        int s0 = g_bucket[e], s1 = g_bucket[e + 1];
        float4 v0 = *(const float4*)&g_tu[(size_t)s0 * 128 + lane * 4];
        float4 v1 = *(const float4*)&g_tu[(size_t)s1 * 128 + lane * 4];
        acc.x += v0.x + v1.x; acc.y += v0.y + v1.y;
        acc.z += v0.z + v1.z; acc.w += v0.w + v1.w;
    }
    for (; e < end; ++e) {
        int s = g_bucket[e];
        float4 v = *(const float4*)&g_tu[(size_t)s * 128 + lane * 4];
        acc.x += v.x; acc.y += v.y; acc.z += v.z; acc.w += v.w;
    }
    float inv = (end > beg) ? 1.f / (float)(end - beg) : 0.f;
    float4 u = *(const float4*)&g_tu[(size_t)node * 128 + 64 + lane * 4];
    float4 bv = *(const float4*)&b2[lane * 4];
    float4 o;
    o.x = 1.f / (1.f + __expf(-(acc.x * inv + u.x + bv.x)));
    o.y = 1.f / (1.f + __expf(-(acc.y * inv + u.y + bv.y)));
    o.z = 1.f / (1.f + __expf(-(acc.z * inv + u.z + bv.z)));
    o.w = 1.f / (1.f + __expf(-(acc.w * inv + u.w + bv.w)));
    *(float4*)&out[(size_t)node * 64 + lane * 4] = o;
}

// ---------------- launch ----------------
extern "C" void kernel_launch(void* const* d_in, const int* in_sizes, int n_in,
                              void* d_out, int out_size) {
    const float* x   = (const float*)d_in[0];
    const void*  ei  = d_in[1];
    const float* W1l = (const float*)d_in[2];
    const float* W1r = (const float*)d_in[3];
    const float* b1  = (const float*)d_in[4];
    const float* W2l = (const float*)d_in[5];
    const float* W2r = (const float*)d_in[6];
    const float* b2  = (const float*)d_in[7];
    float* out = (float*)d_out;

    int N = in_sizes[0] / 128;
    int E = in_sizes[1] / 2;
    int B = (N + 1023) / 1024;

    detect_kernel<<<1, 64>>>((const int*)ei);
    zero_deg_kernel<<<(N + 255) / 256, 256>>>(N);
    count_kernel<<<(E + 255) / 256, 256>>>(ei, E, N);
    scan_blocks<<<B, 1024>>>(N);
    scan_bsums<<<1, 32>>>(B);
    finalize_off<<<(N + 255) / 256, 256>>>(N, E);
    fill_kernel<<<(E + 255) / 256, 256>>>(ei, E, N);

    agg128_kernel<<<(N + 3) / 4, 128>>>(x, N);
    {
        dim3 grid(2, (N + 127) / 128);
        gemm_tc<0><<<grid, 256>>>(x, W1l, W1r, b1, N);
    }
    {
        dim3 grid(1, (N + 127) / 128);
        gemm_tc<1><<<grid, 256>>>(nullptr, W2l, W2r, nullptr, N);
    }
    agg_sig_kernel<<<(N + 7) / 8, 128>>>(b2, out, N);
}